// round 1
// baseline (speedup 1.0000x reference)
#include <cuda_runtime.h>

#define BATCH 8
#define SEQ   2048
#define HID   1024
#define NEG_INF_V (-1e9f)
#define LN_EPS 1e-12f

// ---------------- scratch (device globals: allocation-free) ----------------
__device__ float g_Q[(size_t)BATCH * SEQ * HID];   // 64 MB; reused for context
__device__ float g_K[(size_t)BATCH * SEQ * HID];   // 64 MB
__device__ float g_S[(size_t)BATCH * SEQ * SEQ];   // 134 MB (scores/probs)

// ---------------- SGEMM: 128x128x16 tile, 8x8 per thread, 256 threads ------
#define BMg 128
#define BNg 128
#define BKg 16
#define SPAD 4   // keeps 16B alignment (132 floats * 4B = 528B, mult of 16)

// BT=false: C[m,n] = sum_k A[m,k]*B[k,n]   (B row-major [K,N])
// BT=true : C[m,n] = sum_k A[m,k]*B[n,k]   (B row-major [N,K])
template<bool BT, bool BIAS>
__global__ __launch_bounds__(256, 2)
void sgemm_k(const float* __restrict__ A, const float* __restrict__ B,
             const float* __restrict__ bias, float* __restrict__ C,
             int M, int N, int K,
             long long sA, long long sB, long long sC)
{
    __shared__ float As[BKg][BMg + SPAD];
    __shared__ float Bs[BKg][BNg + SPAD];

    const float* Ab = A + (long long)blockIdx.z * sA;
    const float* Bb = B + (long long)blockIdx.z * sB;
    float*       Cb = C + (long long)blockIdx.z * sC;

    const int bm  = blockIdx.y * BMg;
    const int bn  = blockIdx.x * BNg;
    const int tid = threadIdx.x;
    const int tx  = tid & 15;   // 0..15 -> output cols tx*8..
    const int ty  = tid >> 4;   // 0..15 -> output rows ty*8..

    float acc[8][8];
    #pragma unroll
    for (int i = 0; i < 8; ++i)
        #pragma unroll
        for (int j = 0; j < 8; ++j) acc[i][j] = 0.f;

    for (int k0 = 0; k0 < K; k0 += BKg) {
        // ---- load A tile [BM x BK], store transposed As[k][m] ----
        #pragma unroll
        for (int i = 0; i < 2; ++i) {
            int f  = tid + i * 256;        // 0..511 float4 id
            int r  = f >> 2;               // 0..127 row within tile
            int c4 = (f & 3) * 4;          // 0,4,8,12 col within BK
            float4 v = *reinterpret_cast<const float4*>(
                &Ab[(long long)(bm + r) * K + k0 + c4]);
            As[c4 + 0][r] = v.x; As[c4 + 1][r] = v.y;
            As[c4 + 2][r] = v.z; As[c4 + 3][r] = v.w;
        }
        // ---- load B tile into Bs[k][n] ----
        if (BT) {
            #pragma unroll
            for (int i = 0; i < 2; ++i) {
                int f  = tid + i * 256;
                int r  = f >> 2;           // n within tile
                int c4 = (f & 3) * 4;      // k within BK
                float4 v = *reinterpret_cast<const float4*>(
                    &Bb[(long long)(bn + r) * K + k0 + c4]);
                Bs[c4 + 0][r] = v.x; Bs[c4 + 1][r] = v.y;
                Bs[c4 + 2][r] = v.z; Bs[c4 + 3][r] = v.w;
            }
        } else {
            #pragma unroll
            for (int i = 0; i < 2; ++i) {
                int f = tid + i * 256;
                int r = f >> 5;            // 0..15 k within BK
                int c = (f & 31) * 4;      // 0..124 n within tile
                *reinterpret_cast<float4*>(&Bs[r][c]) =
                    *reinterpret_cast<const float4*>(
                        &Bb[(long long)(k0 + r) * N + bn + c]);
            }
        }
        __syncthreads();

        // ---- compute ----
        #pragma unroll
        for (int kk = 0; kk < BKg; ++kk) {
            float a[8], b[8];
            *reinterpret_cast<float4*>(a)     = *reinterpret_cast<const float4*>(&As[kk][ty * 8]);
            *reinterpret_cast<float4*>(a + 4) = *reinterpret_cast<const float4*>(&As[kk][ty * 8 + 4]);
            *reinterpret_cast<float4*>(b)     = *reinterpret_cast<const float4*>(&Bs[kk][tx * 8]);
            *reinterpret_cast<float4*>(b + 4) = *reinterpret_cast<const float4*>(&Bs[kk][tx * 8 + 4]);
            #pragma unroll
            for (int i = 0; i < 8; ++i)
                #pragma unroll
                for (int j = 0; j < 8; ++j)
                    acc[i][j] += a[i] * b[j];
        }
        __syncthreads();
    }

    float bv[8];
    if (BIAS) {
        #pragma unroll
        for (int j = 0; j < 8; ++j) bv[j] = bias[bn + tx * 8 + j];
    }
    #pragma unroll
    for (int i = 0; i < 8; ++i) {
        long long row = bm + ty * 8 + i;
        if (BIAS) {
            #pragma unroll
            for (int j = 0; j < 8; ++j) acc[i][j] += bv[j];
        }
        *reinterpret_cast<float4*>(&Cb[row * N + bn + tx * 8]) =
            make_float4(acc[i][0], acc[i][1], acc[i][2], acc[i][3]);
        *reinterpret_cast<float4*>(&Cb[row * N + bn + tx * 8 + 4]) =
            make_float4(acc[i][4], acc[i][5], acc[i][6], acc[i][7]);
    }
}

// ---------------- masked + scaled softmax, in place, one block per row -----
__global__ __launch_bounds__(256)
void softmax_k(float* __restrict__ S, const int* __restrict__ masks, float scale)
{
    const size_t row = blockIdx.x;            // b*SEQ + q
    const int b = (int)(row / SEQ);
    float* p = S + row * (size_t)SEQ;
    const int* mrow = masks + (size_t)b * SEQ;

    __shared__ float red[256];
    float v[8];
    float mx = -3e38f;
    #pragma unroll
    for (int i = 0; i < 8; ++i) {
        int k = threadIdx.x + i * 256;
        float s = p[k];
        s = mrow[k] ? s * scale : NEG_INF_V;
        v[i] = s;
        mx = fmaxf(mx, s);
    }
    red[threadIdx.x] = mx;
    __syncthreads();
    #pragma unroll
    for (int s2 = 128; s2 > 0; s2 >>= 1) {
        if (threadIdx.x < s2)
            red[threadIdx.x] = fmaxf(red[threadIdx.x], red[threadIdx.x + s2]);
        __syncthreads();
    }
    mx = red[0];
    __syncthreads();

    float sum = 0.f;
    #pragma unroll
    for (int i = 0; i < 8; ++i) { v[i] = __expf(v[i] - mx); sum += v[i]; }
    red[threadIdx.x] = sum;
    __syncthreads();
    #pragma unroll
    for (int s2 = 128; s2 > 0; s2 >>= 1) {
        if (threadIdx.x < s2)
            red[threadIdx.x] += red[threadIdx.x + s2];
        __syncthreads();
    }
    const float inv = 1.0f / red[0];
    #pragma unroll
    for (int i = 0; i < 8; ++i) {
        int k = threadIdx.x + i * 256;
        p[k] = v[i] * inv;
    }
}

// ---------------- residual + LayerNorm, one block per row ------------------
__global__ __launch_bounds__(256)
void ln_k(const float* __restrict__ X, const float* __restrict__ Cx,
          const float* __restrict__ gamma, const float* __restrict__ beta,
          float* __restrict__ out)
{
    const size_t row = blockIdx.x;
    const float* x = X  + row * (size_t)HID;
    const float* c = Cx + row * (size_t)HID;

    __shared__ float red[256];
    float v[4];
    float s = 0.f;
    #pragma unroll
    for (int i = 0; i < 4; ++i) {
        int k = threadIdx.x + i * 256;
        v[i] = x[k] + c[k];
        s += v[i];
    }
    red[threadIdx.x] = s;
    __syncthreads();
    #pragma unroll
    for (int s2 = 128; s2 > 0; s2 >>= 1) {
        if (threadIdx.x < s2) red[threadIdx.x] += red[threadIdx.x + s2];
        __syncthreads();
    }
    const float mu = red[0] * (1.0f / HID);
    __syncthreads();

    float s2v = 0.f;
    #pragma unroll
    for (int i = 0; i < 4; ++i) { float d = v[i] - mu; s2v += d * d; }
    red[threadIdx.x] = s2v;
    __syncthreads();
    #pragma unroll
    for (int s2 = 128; s2 > 0; s2 >>= 1) {
        if (threadIdx.x < s2) red[threadIdx.x] += red[threadIdx.x + s2];
        __syncthreads();
    }
    const float var = red[0] * (1.0f / HID);
    const float r = rsqrtf(var + LN_EPS);
    #pragma unroll
    for (int i = 0; i < 4; ++i) {
        int k = threadIdx.x + i * 256;
        out[row * (size_t)HID + k] = (v[i] - mu) * r * gamma[k] + beta[k];
    }
}

// ---------------- launch ---------------------------------------------------
extern "C" void kernel_launch(void* const* d_in, const int* in_sizes, int n_in,
                              void* d_out, int out_size)
{
    const float* inputs = (const float*)d_in[0];
    const int*   masks  = (const int*)  d_in[1];
    const float* Wq     = (const float*)d_in[2];
    const float* bq     = (const float*)d_in[3];
    const float* Wk     = (const float*)d_in[4];
    const float* bk     = (const float*)d_in[5];
    const float* gamma  = (const float*)d_in[6];
    const float* beta   = (const float*)d_in[7];
    float* out = (float*)d_out;

    float *Qp, *Kp, *Sp;
    cudaGetSymbolAddress((void**)&Qp, g_Q);
    cudaGetSymbolAddress((void**)&Kp, g_K);
    cudaGetSymbolAddress((void**)&Sp, g_S);

    const int M = BATCH * SEQ;             // 16384
    const long long sSH = (long long)SEQ * HID;
    const long long sSS = (long long)SEQ * SEQ;
    const float scale = 0.03125f;          // 1/sqrt(1024)

    // Q = X Wq + bq ; K = X Wk + bk   (NN, bias epilogue)
    sgemm_k<false, true><<<dim3(HID / BNg, M / BMg, 1), 256>>>(
        inputs, Wq, bq, Qp, M, HID, HID, 0, 0, 0);
    sgemm_k<false, true><<<dim3(HID / BNg, M / BMg, 1), 256>>>(
        inputs, Wk, bk, Kp, M, HID, HID, 0, 0, 0);

    // scores = Q K^T per batch (NT)
    sgemm_k<true, false><<<dim3(SEQ / BNg, SEQ / BMg, BATCH), 256>>>(
        Qp, Kp, nullptr, Sp, SEQ, SEQ, HID, sSH, sSH, sSS);

    // masked, scaled softmax in place
    softmax_k<<<M, 256>>>(Sp, masks, scale);

    // context = probs @ X per batch (NN), reuse Q buffer for context
    sgemm_k<false, false><<<dim3(HID / BNg, SEQ / BMg, BATCH), 256>>>(
        Sp, inputs, nullptr, Qp, SEQ, HID, SEQ, sSS, sSH, sSH);

    // out = LN(X + context)
    ln_k<<<M, 256>>>(inputs, Qp, gamma, beta, out);
}

// round 4
// speedup vs baseline: 2.8465x; 2.8465x over previous
#include <cuda_runtime.h>
#include <cuda_bf16.h>
#include <cstdint>

#define BATCH 8
#define SEQ   2048
#define HID   1024
#define NEG_INF_V (-1e9f)
#define LN_EPS 1e-12f

// ---------------- scratch (device globals: allocation-free) ----------------
__device__ float          g_S [(size_t)BATCH * SEQ * SEQ];   // scores fp32, reused for context fp32
__device__ __nv_bfloat16  g_P [(size_t)BATCH * SEQ * SEQ];   // probs bf16
__device__ __nv_bfloat16  g_Xb[(size_t)BATCH * SEQ * HID];   // inputs bf16 (row-major)
__device__ __nv_bfloat16  g_XT[(size_t)BATCH * HID * SEQ];   // inputs^T bf16
__device__ __nv_bfloat16  g_Qb[(size_t)BATCH * SEQ * HID];   // Q bf16
__device__ __nv_bfloat16  g_Kb[(size_t)BATCH * SEQ * HID];   // K bf16
__device__ __nv_bfloat16  g_Wq[(size_t)HID * HID];           // Wq^T bf16 [N][K]
__device__ __nv_bfloat16  g_Wk[(size_t)HID * HID];           // Wk^T bf16 [N][K]

// ======================= helpers ===========================================
__device__ __forceinline__ uint32_t smem_u32(const void* p) {
    uint32_t a;
    asm("{ .reg .u64 t; cvta.to.shared.u64 t, %1; cvt.u32.u64 %0, t; }"
        : "=r"(a) : "l"(p));
    return a;
}
#define CP_ASYNC16(s, g) \
    asm volatile("cp.async.cg.shared.global [%0], [%1], 16;" :: "r"(s), "l"(g))
#define CP_COMMIT() asm volatile("cp.async.commit_group;")
#define CP_WAIT2()  asm volatile("cp.async.wait_group 2;")

#define LDSM4(r, addr) \
    asm volatile("ldmatrix.sync.aligned.m8n8.x4.shared.b16 {%0,%1,%2,%3}, [%4];" \
        : "=r"((r)[0]), "=r"((r)[1]), "=r"((r)[2]), "=r"((r)[3]) : "r"(addr))

#define MMA16816(d, a, b0, b1) \
    asm volatile("mma.sync.aligned.m16n8k16.row.col.f32.bf16.bf16.f32 " \
        "{%0,%1,%2,%3}, {%4,%5,%6,%7}, {%8,%9}, {%0,%1,%2,%3};" \
        : "+f"((d)[0]), "+f"((d)[1]), "+f"((d)[2]), "+f"((d)[3]) \
        : "r"((a)[0]), "r"((a)[1]), "r"((a)[2]), "r"((a)[3]), "r"(b0), "r"(b1))

// ======================= bf16 HMMA GEMM ====================================
// C[m,n] = sum_k A[m,k] * B[n,k] ; A [M,K], B [N,K], both bf16 K-major.
#define GBM 128
#define GBN 128
#define GBK 32
#define STAGES 4
#define ROWB 80                       // 64B data + 16B pad per smem row
#define TILEB (128 * ROWB)            // 10240 B
#define STAGEB (2 * TILEB)            // A + B
#define SMEM_GEMM (STAGES * STAGEB)   // 81920 B

template<bool BF16_OUT, bool HAS_BIAS>
__global__ __launch_bounds__(256, 1)
void hgemm(const __nv_bfloat16* __restrict__ A, const __nv_bfloat16* __restrict__ B,
           const float* __restrict__ bias, void* __restrict__ Cv,
           int M, int N, int K,
           long long sA, long long sB, long long sC)
{
    extern __shared__ char sm[];
    const __nv_bfloat16* Ab = A + (long long)blockIdx.z * sA;
    const __nv_bfloat16* Bb = B + (long long)blockIdx.z * sB;

    const int bm = blockIdx.y * GBM;
    const int bn = blockIdx.x * GBN;
    const int tid = threadIdx.x;
    const int wid = tid >> 5, lane = tid & 31;
    const int wm = (wid >> 2) * 64;    // warp row offset (0 or 64)
    const int wn = (wid & 3) * 32;     // warp col offset (0..96)

    float acc[4][4][4];
    #pragma unroll
    for (int i = 0; i < 4; ++i)
        #pragma unroll
        for (int j = 0; j < 4; ++j)
            #pragma unroll
            for (int q = 0; q < 4; ++q) acc[i][j][q] = 0.f;

    const int NC = K / GBK;

    // ---- async tile loader (each thread: 2 A chunks + 2 B chunks of 16B) --
    auto issue = [&](int chunk, int stage) {
        char* base = sm + stage * STAGEB;
        const int k0 = chunk * GBK;
        #pragma unroll
        for (int i = 0; i < 2; ++i) {
            int cc  = tid + i * 256;         // 0..511
            int row = cc >> 2;               // 0..127
            int q   = cc & 3;                // 16B chunk within 64B row
            uint32_t sa = smem_u32(base + row * ROWB + q * 16);
            const void* ga = Ab + (long long)(bm + row) * K + k0 + q * 8;
            CP_ASYNC16(sa, ga);
            uint32_t sb = smem_u32(base + TILEB + row * ROWB + q * 16);
            const void* gb = Bb + (long long)(bn + row) * K + k0 + q * 8;
            CP_ASYNC16(sb, gb);
        }
    };

    // prologue: fill STAGES-1 stages
    #pragma unroll
    for (int s = 0; s < STAGES - 1; ++s) { issue(s, s); CP_COMMIT(); }

    for (int c = 0; c < NC; ++c) {
        CP_WAIT2();
        __syncthreads();

        const int stg = c & (STAGES - 1);
        const uint32_t abase = smem_u32(sm + stg * STAGEB);
        const uint32_t bbase = abase + TILEB;

        #pragma unroll
        for (int ks = 0; ks < 2; ++ks) {
            uint32_t a[4][4], b[2][4];
            #pragma unroll
            for (int t = 0; t < 4; ++t) {
                uint32_t addr = abase
                    + (uint32_t)(wm + t * 16 + (lane & 15)) * ROWB
                    + ks * 32 + ((lane >> 4) << 4);
                LDSM4(a[t], addr);
            }
            #pragma unroll
            for (int u = 0; u < 2; ++u) {
                uint32_t addr = bbase
                    + (uint32_t)(wn + u * 16 + ((lane >> 4) << 3) + (lane & 7)) * ROWB
                    + ks * 32 + (((lane >> 3) & 1) << 4);
                LDSM4(b[u], addr);
            }
            #pragma unroll
            for (int tm = 0; tm < 4; ++tm)
                #pragma unroll
                for (int j = 0; j < 4; ++j)
                    MMA16816(acc[tm][j], a[tm],
                             b[j >> 1][(j & 1) * 2], b[j >> 1][(j & 1) * 2 + 1]);
        }
        __syncthreads();

        if (c + STAGES - 1 < NC) issue(c + STAGES - 1, (c + STAGES - 1) & (STAGES - 1));
        CP_COMMIT();   // empty group in tail keeps wait_group bookkeeping uniform
    }

    // ---- epilogue: direct global stores ----
    const int qr = lane >> 2;            // 0..7
    const int qc = (lane & 3) * 2;       // 0,2,4,6
    #pragma unroll
    for (int tm = 0; tm < 4; ++tm) {
        #pragma unroll
        for (int j = 0; j < 4; ++j) {
            const long long n0 = bn + wn + j * 8 + qc;
            const long long m0 = bm + wm + tm * 16 + qr;
            float b0 = 0.f, b1 = 0.f;
            if (HAS_BIAS) { b0 = bias[n0]; b1 = bias[n0 + 1]; }
            if (BF16_OUT) {
                __nv_bfloat16* C = (__nv_bfloat16*)Cv + (long long)blockIdx.z * sC;
                __nv_bfloat162 lo = __float22bfloat162_rn(
                    make_float2(acc[tm][j][0] + b0, acc[tm][j][1] + b1));
                __nv_bfloat162 hi = __float22bfloat162_rn(
                    make_float2(acc[tm][j][2] + b0, acc[tm][j][3] + b1));
                *reinterpret_cast<uint32_t*>(C + m0 * N + n0)       = *reinterpret_cast<uint32_t*>(&lo);
                *reinterpret_cast<uint32_t*>(C + (m0 + 8) * N + n0) = *reinterpret_cast<uint32_t*>(&hi);
            } else {
                float* C = (float*)Cv + (long long)blockIdx.z * sC;
                *reinterpret_cast<float2*>(C + m0 * N + n0) =
                    make_float2(acc[tm][j][0] + b0, acc[tm][j][1] + b1);
                *reinterpret_cast<float2*>(C + (m0 + 8) * N + n0) =
                    make_float2(acc[tm][j][2] + b0, acc[tm][j][3] + b1);
            }
        }
    }
}

// ---------------- fp32 -> bf16 copy ----------------------------------------
__global__ __launch_bounds__(256)
void cvt_bf16_k(const float* __restrict__ in, __nv_bfloat16* __restrict__ out)
{
    size_t i = ((size_t)blockIdx.x * 256 + threadIdx.x) * 4;
    float4 v = *reinterpret_cast<const float4*>(in + i);
    __nv_bfloat162 a = __float22bfloat162_rn(make_float2(v.x, v.y));
    __nv_bfloat162 b = __float22bfloat162_rn(make_float2(v.z, v.w));
    uint2 pk = make_uint2(*reinterpret_cast<uint32_t*>(&a), *reinterpret_cast<uint32_t*>(&b));
    *reinterpret_cast<uint2*>(out + i) = pk;
}

// ---------------- fp32 [R,C] -> bf16 [C,R] transpose -----------------------
__global__ __launch_bounds__(256)
void transpose_bf16_k(const float* __restrict__ in, __nv_bfloat16* __restrict__ out,
                      int R, int C, long long sIn, long long sOut)
{
    __shared__ float t[32][33];
    const float* ib = in + (long long)blockIdx.z * sIn;
    __nv_bfloat16* ob = out + (long long)blockIdx.z * sOut;
    int c0 = blockIdx.x * 32, r0 = blockIdx.y * 32;
    int tx = threadIdx.x & 31, ty = threadIdx.x >> 5;   // 32 x 8
    #pragma unroll
    for (int j = 0; j < 4; ++j)
        t[ty + j * 8][tx] = ib[(long long)(r0 + ty + j * 8) * C + c0 + tx];
    __syncthreads();
    #pragma unroll
    for (int j = 0; j < 4; ++j)
        ob[(long long)(c0 + ty + j * 8) * R + r0 + tx] =
            __float2bfloat16(t[tx][ty + j * 8]);
}

// ---------------- masked + scaled softmax: fp32 in, bf16 out ---------------
__global__ __launch_bounds__(256)
void softmax_k(const float* __restrict__ S, __nv_bfloat16* __restrict__ P,
               const int* __restrict__ masks, float scale)
{
    const size_t row = blockIdx.x;
    const int b = (int)(row / SEQ);
    const float* p = S + row * (size_t)SEQ;
    __nv_bfloat16* o = P + row * (size_t)SEQ;
    const int* mrow = masks + (size_t)b * SEQ;
    const int k0 = threadIdx.x * 8;

    __shared__ float red[256];
    float v[8];
    float mx = -3e38f;
    #pragma unroll
    for (int i = 0; i < 2; ++i) {
        float4 s4 = *reinterpret_cast<const float4*>(p + k0 + i * 4);
        int4   m4 = *reinterpret_cast<const int4*>(mrow + k0 + i * 4);
        v[i*4+0] = m4.x ? s4.x * scale : NEG_INF_V;
        v[i*4+1] = m4.y ? s4.y * scale : NEG_INF_V;
        v[i*4+2] = m4.z ? s4.z * scale : NEG_INF_V;
        v[i*4+3] = m4.w ? s4.w * scale : NEG_INF_V;
    }
    #pragma unroll
    for (int i = 0; i < 8; ++i) mx = fmaxf(mx, v[i]);
    red[threadIdx.x] = mx;
    __syncthreads();
    #pragma unroll
    for (int s2 = 128; s2 > 0; s2 >>= 1) {
        if (threadIdx.x < s2)
            red[threadIdx.x] = fmaxf(red[threadIdx.x], red[threadIdx.x + s2]);
        __syncthreads();
    }
    mx = red[0];
    __syncthreads();

    float sum = 0.f;
    #pragma unroll
    for (int i = 0; i < 8; ++i) { v[i] = __expf(v[i] - mx); sum += v[i]; }
    red[threadIdx.x] = sum;
    __syncthreads();
    #pragma unroll
    for (int s2 = 128; s2 > 0; s2 >>= 1) {
        if (threadIdx.x < s2) red[threadIdx.x] += red[threadIdx.x + s2];
        __syncthreads();
    }
    const float inv = 1.0f / red[0];

    uint4 pk;
    __nv_bfloat162 h;
    h = __float22bfloat162_rn(make_float2(v[0]*inv, v[1]*inv)); pk.x = *reinterpret_cast<uint32_t*>(&h);
    h = __float22bfloat162_rn(make_float2(v[2]*inv, v[3]*inv)); pk.y = *reinterpret_cast<uint32_t*>(&h);
    h = __float22bfloat162_rn(make_float2(v[4]*inv, v[5]*inv)); pk.z = *reinterpret_cast<uint32_t*>(&h);
    h = __float22bfloat162_rn(make_float2(v[6]*inv, v[7]*inv)); pk.w = *reinterpret_cast<uint32_t*>(&h);
    *reinterpret_cast<uint4*>(o + k0) = pk;
}

// ---------------- residual + LayerNorm -------------------------------------
__global__ __launch_bounds__(256)
void ln_k(const float* __restrict__ X, const float* __restrict__ Cx,
          const float* __restrict__ gamma, const float* __restrict__ beta,
          float* __restrict__ out)
{
    const size_t row = blockIdx.x;
    const float* x = X  + row * (size_t)HID;
    const float* c = Cx + row * (size_t)HID;

    __shared__ float red[256];
    float v[4];
    float s = 0.f;
    #pragma unroll
    for (int i = 0; i < 4; ++i) {
        int k = threadIdx.x + i * 256;
        v[i] = x[k] + c[k];
        s += v[i];
    }
    red[threadIdx.x] = s;
    __syncthreads();
    #pragma unroll
    for (int s2 = 128; s2 > 0; s2 >>= 1) {
        if (threadIdx.x < s2) red[threadIdx.x] += red[threadIdx.x + s2];
        __syncthreads();
    }
    const float mu = red[0] * (1.0f / HID);
    __syncthreads();

    float s2v = 0.f;
    #pragma unroll
    for (int i = 0; i < 4; ++i) { float d = v[i] - mu; s2v += d * d; }
    red[threadIdx.x] = s2v;
    __syncthreads();
    #pragma unroll
    for (int s2 = 128; s2 > 0; s2 >>= 1) {
        if (threadIdx.x < s2) red[threadIdx.x] += red[threadIdx.x + s2];
        __syncthreads();
    }
    const float var = red[0] * (1.0f / HID);
    const float r = rsqrtf(var + LN_EPS);
    #pragma unroll
    for (int i = 0; i < 4; ++i) {
        int k = threadIdx.x + i * 256;
        out[row * (size_t)HID + k] = (v[i] - mu) * r * gamma[k] + beta[k];
    }
}

// ---------------- launch ---------------------------------------------------
extern "C" void kernel_launch(void* const* d_in, const int* in_sizes, int n_in,
                              void* d_out, int out_size)
{
    const float* inputs = (const float*)d_in[0];
    const int*   masks  = (const int*)  d_in[1];
    const float* Wq     = (const float*)d_in[2];
    const float* bq     = (const float*)d_in[3];
    const float* Wk     = (const float*)d_in[4];
    const float* bk     = (const float*)d_in[5];
    const float* gamma  = (const float*)d_in[6];
    const float* beta   = (const float*)d_in[7];
    float* out = (float*)d_out;

    float *Sp;
    __nv_bfloat16 *Pp, *Xbp, *XTp, *Qp, *Kp, *Wqp, *Wkp;
    cudaGetSymbolAddress((void**)&Sp,  g_S);
    cudaGetSymbolAddress((void**)&Pp,  g_P);
    cudaGetSymbolAddress((void**)&Xbp, g_Xb);
    cudaGetSymbolAddress((void**)&XTp, g_XT);
    cudaGetSymbolAddress((void**)&Qp,  g_Qb);
    cudaGetSymbolAddress((void**)&Kp,  g_Kb);
    cudaGetSymbolAddress((void**)&Wqp, g_Wq);
    cudaGetSymbolAddress((void**)&Wkp, g_Wk);

    const int M = BATCH * SEQ;                       // 16384
    const long long sSH = (long long)SEQ * HID;
    const long long sSS = (long long)SEQ * SEQ;
    const long long sHS = (long long)HID * SEQ;
    const float scale = 0.03125f;                    // 1/sqrt(1024)

    cudaFuncSetAttribute(hgemm<true,  true >, cudaFuncAttributeMaxDynamicSharedMemorySize, SMEM_GEMM);
    cudaFuncSetAttribute(hgemm<false, false>, cudaFuncAttributeMaxDynamicSharedMemorySize, SMEM_GEMM);

    // bf16 conversions / transposes
    cvt_bf16_k<<<(unsigned)((size_t)M * HID / (256 * 4)), 256>>>(inputs, Xbp);
    transpose_bf16_k<<<dim3(HID/32, SEQ/32, BATCH), 256>>>(inputs, XTp, SEQ, HID, sSH, sHS);
    transpose_bf16_k<<<dim3(HID/32, HID/32, 1), 256>>>(Wq, Wqp, HID, HID, 0, 0);
    transpose_bf16_k<<<dim3(HID/32, HID/32, 1), 256>>>(Wk, Wkp, HID, HID, 0, 0);

    // Q = X Wq + bq ; K = X Wk + bk  -> bf16
    hgemm<true, true><<<dim3(HID/GBN, M/GBM, 1), 256, SMEM_GEMM>>>(
        Xbp, Wqp, bq, Qp, M, HID, HID, 0, 0, 0);
    hgemm<true, true><<<dim3(HID/GBN, M/GBM, 1), 256, SMEM_GEMM>>>(
        Xbp, Wkp, bk, Kp, M, HID, HID, 0, 0, 0);

    // scores = Q K^T per batch -> fp32
    hgemm<false, false><<<dim3(SEQ/GBN, SEQ/GBM, BATCH), 256, SMEM_GEMM>>>(
        Qp, Kp, nullptr, Sp, SEQ, SEQ, HID, sSH, sSH, sSS);

    // masked, scaled softmax -> bf16 probs
    softmax_k<<<M, 256>>>(Sp, Pp, masks, scale);

    // context = probs @ X per batch -> fp32 (reuse g_S)
    hgemm<false, false><<<dim3(HID/GBN, SEQ/GBM, BATCH), 256, SMEM_GEMM>>>(
        Pp, XTp, nullptr, Sp, SEQ, HID, SEQ, sSS, sHS, sSH);

    // out = LN(X + context)
    ln_k<<<M, 256>>>(inputs, Sp, gamma, beta, out);
}

// round 5
// speedup vs baseline: 5.9282x; 2.0826x over previous
#include <cuda_runtime.h>
#include <cuda_bf16.h>
#include <cstdint>

#define BATCH 8
#define SEQ   2048
#define HID   1024
#define NEG_INF_V (-1e9f)
#define LN_EPS 1e-12f

// ---------------- scratch (device globals: allocation-free) ----------------
__device__ float          g_S [(size_t)BATCH * SEQ * SEQ];   // scores fp32, reused for context fp32
__device__ __nv_bfloat16  g_P [(size_t)BATCH * SEQ * SEQ];   // probs bf16
__device__ __nv_bfloat16  g_Xb[(size_t)BATCH * SEQ * HID];   // inputs bf16 (row-major)
__device__ __nv_bfloat16  g_XT[(size_t)BATCH * HID * SEQ];   // inputs^T bf16
__device__ __nv_bfloat16  g_Qb[(size_t)BATCH * SEQ * HID];   // Q bf16
__device__ __nv_bfloat16  g_Kb[(size_t)BATCH * SEQ * HID];   // K bf16
__device__ __nv_bfloat16  g_Wq[(size_t)HID * HID];           // Wq^T bf16 [N][K]
__device__ __nv_bfloat16  g_Wk[(size_t)HID * HID];           // Wk^T bf16 [N][K]

// ======================= helpers ===========================================
__device__ __forceinline__ uint32_t smem_u32(const void* p) {
    uint32_t a;
    asm("{ .reg .u64 t; cvta.to.shared.u64 t, %1; cvt.u32.u64 %0, t; }"
        : "=r"(a) : "l"(p));
    return a;
}
#define CP_ASYNC16(s, g) \
    asm volatile("cp.async.cg.shared.global [%0], [%1], 16;" :: "r"(s), "l"(g))
#define CP_COMMIT() asm volatile("cp.async.commit_group;")
#define CP_WAIT1()  asm volatile("cp.async.wait_group 1;")

#define LDSM4(r, addr) \
    asm volatile("ldmatrix.sync.aligned.m8n8.x4.shared.b16 {%0,%1,%2,%3}, [%4];" \
        : "=r"((r)[0]), "=r"((r)[1]), "=r"((r)[2]), "=r"((r)[3]) : "r"(addr))

#define MMA16816(d, a, b0, b1) \
    asm volatile("mma.sync.aligned.m16n8k16.row.col.f32.bf16.bf16.f32 " \
        "{%0,%1,%2,%3}, {%4,%5,%6,%7}, {%8,%9}, {%0,%1,%2,%3};" \
        : "+f"((d)[0]), "+f"((d)[1]), "+f"((d)[2]), "+f"((d)[3]) \
        : "r"((a)[0]), "r"((a)[1]), "r"((a)[2]), "r"((a)[3]), "r"(b0), "r"(b1))

// ======================= bf16 HMMA GEMM ====================================
// C[m,n] = sum_k A[m,k] * B[n,k] ; A [M,K], B [N,K], both bf16 K-major.
#define GBM 128
#define GBN 128
#define GBK 32
#define STAGES 3
#define ROWB 80                       // 64B data + 16B pad per smem row
#define TILEB (128 * ROWB)            // 10240 B
#define STAGEB (2 * TILEB)            // A + B
#define SMEM_GEMM (STAGES * STAGEB)   // 61440 B -> 2 CTAs/SM

template<bool BF16_OUT, bool HAS_BIAS>
__global__ __launch_bounds__(256, 2)
void hgemm(const __nv_bfloat16* __restrict__ A, const __nv_bfloat16* __restrict__ B,
           const float* __restrict__ bias, void* __restrict__ Cv,
           int M, int N, int K,
           long long sA, long long sB, long long sC)
{
    extern __shared__ char sm[];
    const __nv_bfloat16* Ab = A + (long long)blockIdx.z * sA;
    const __nv_bfloat16* Bb = B + (long long)blockIdx.z * sB;

    const int bm = blockIdx.y * GBM;
    const int bn = blockIdx.x * GBN;
    const int tid = threadIdx.x;
    const int wid = tid >> 5, lane = tid & 31;
    const int wm = (wid >> 2) * 64;    // warp row offset (0 or 64)
    const int wn = (wid & 3) * 32;     // warp col offset (0..96)

    float acc[4][4][4];
    #pragma unroll
    for (int i = 0; i < 4; ++i)
        #pragma unroll
        for (int j = 0; j < 4; ++j)
            #pragma unroll
            for (int q = 0; q < 4; ++q) acc[i][j][q] = 0.f;

    const int NC = K / GBK;

    // ---- async tile loader (each thread: 2 A chunks + 2 B chunks of 16B) --
    auto issue = [&](int chunk, int stage) {
        char* base = sm + stage * STAGEB;
        const int k0 = chunk * GBK;
        #pragma unroll
        for (int i = 0; i < 2; ++i) {
            int cc  = tid + i * 256;         // 0..511
            int row = cc >> 2;               // 0..127
            int q   = cc & 3;                // 16B chunk within 64B row
            uint32_t sa = smem_u32(base + row * ROWB + q * 16);
            const void* ga = Ab + (long long)(bm + row) * K + k0 + q * 8;
            CP_ASYNC16(sa, ga);
            uint32_t sb = smem_u32(base + TILEB + row * ROWB + q * 16);
            const void* gb = Bb + (long long)(bn + row) * K + k0 + q * 8;
            CP_ASYNC16(sb, gb);
        }
    };

    // prologue: fill 2 stages
    issue(0, 0); CP_COMMIT();
    issue(1, 1); CP_COMMIT();

    for (int c = 0; c < NC; ++c) {
        CP_WAIT1();            // chunk c resident
        __syncthreads();       // all warps see it; stage (c+2)%3 fully drained

        // prefetch chunk c+2 into the stage consumed at iter c-1
        const int nc = c + 2;
        if (nc < NC) issue(nc, nc % 3);
        CP_COMMIT();           // empty group in tail keeps bookkeeping uniform

        const int stg = c % 3;
        const uint32_t abase = smem_u32(sm + stg * STAGEB);
        const uint32_t bbase = abase + TILEB;

        #pragma unroll
        for (int ks = 0; ks < 2; ++ks) {
            uint32_t a[4][4], b[2][4];
            #pragma unroll
            for (int t = 0; t < 4; ++t) {
                uint32_t addr = abase
                    + (uint32_t)(wm + t * 16 + (lane & 15)) * ROWB
                    + ks * 32 + ((lane >> 4) << 4);
                LDSM4(a[t], addr);
            }
            #pragma unroll
            for (int u = 0; u < 2; ++u) {
                uint32_t addr = bbase
                    + (uint32_t)(wn + u * 16 + ((lane >> 4) << 3) + (lane & 7)) * ROWB
                    + ks * 32 + (((lane >> 3) & 1) << 4);
                LDSM4(b[u], addr);
            }
            #pragma unroll
            for (int tm = 0; tm < 4; ++tm)
                #pragma unroll
                for (int j = 0; j < 4; ++j)
                    MMA16816(acc[tm][j], a[tm],
                             b[j >> 1][(j & 1) * 2], b[j >> 1][(j & 1) * 2 + 1]);
        }
    }

    // ---- epilogue: direct global stores ----
    const int qr = lane >> 2;            // 0..7
    const int qc = (lane & 3) * 2;       // 0,2,4,6
    #pragma unroll
    for (int tm = 0; tm < 4; ++tm) {
        #pragma unroll
        for (int j = 0; j < 4; ++j) {
            const long long n0 = bn + wn + j * 8 + qc;
            const long long m0 = bm + wm + tm * 16 + qr;
            float b0 = 0.f, b1 = 0.f;
            if (HAS_BIAS) { b0 = bias[n0]; b1 = bias[n0 + 1]; }
            if (BF16_OUT) {
                __nv_bfloat16* C = (__nv_bfloat16*)Cv + (long long)blockIdx.z * sC;
                __nv_bfloat162 lo = __float22bfloat162_rn(
                    make_float2(acc[tm][j][0] + b0, acc[tm][j][1] + b1));
                __nv_bfloat162 hi = __float22bfloat162_rn(
                    make_float2(acc[tm][j][2] + b0, acc[tm][j][3] + b1));
                *reinterpret_cast<uint32_t*>(C + m0 * N + n0)       = *reinterpret_cast<uint32_t*>(&lo);
                *reinterpret_cast<uint32_t*>(C + (m0 + 8) * N + n0) = *reinterpret_cast<uint32_t*>(&hi);
            } else {
                float* C = (float*)Cv + (long long)blockIdx.z * sC;
                *reinterpret_cast<float2*>(C + m0 * N + n0) =
                    make_float2(acc[tm][j][0] + b0, acc[tm][j][1] + b1);
                *reinterpret_cast<float2*>(C + (m0 + 8) * N + n0) =
                    make_float2(acc[tm][j][2] + b0, acc[tm][j][3] + b1);
            }
        }
    }
}

// ---------------- fp32 -> bf16 copy ----------------------------------------
__global__ __launch_bounds__(256)
void cvt_bf16_k(const float* __restrict__ in, __nv_bfloat16* __restrict__ out)
{
    size_t i = ((size_t)blockIdx.x * 256 + threadIdx.x) * 4;
    float4 v = *reinterpret_cast<const float4*>(in + i);
    __nv_bfloat162 a = __float22bfloat162_rn(make_float2(v.x, v.y));
    __nv_bfloat162 b = __float22bfloat162_rn(make_float2(v.z, v.w));
    uint2 pk = make_uint2(*reinterpret_cast<uint32_t*>(&a), *reinterpret_cast<uint32_t*>(&b));
    *reinterpret_cast<uint2*>(out + i) = pk;
}

// ---------------- fp32 [R,C] -> bf16 [C,R] transpose -----------------------
__global__ __launch_bounds__(256)
void transpose_bf16_k(const float* __restrict__ in, __nv_bfloat16* __restrict__ out,
                      int R, int C, long long sIn, long long sOut)
{
    __shared__ float t[32][33];
    const float* ib = in + (long long)blockIdx.z * sIn;
    __nv_bfloat16* ob = out + (long long)blockIdx.z * sOut;
    int c0 = blockIdx.x * 32, r0 = blockIdx.y * 32;
    int tx = threadIdx.x & 31, ty = threadIdx.x >> 5;   // 32 x 8
    #pragma unroll
    for (int j = 0; j < 4; ++j)
        t[ty + j * 8][tx] = ib[(long long)(r0 + ty + j * 8) * C + c0 + tx];
    __syncthreads();
    #pragma unroll
    for (int j = 0; j < 4; ++j)
        ob[(long long)(c0 + ty + j * 8) * R + r0 + tx] =
            __float2bfloat16(t[tx][ty + j * 8]);
}

// ---------------- masked + scaled softmax: fp32 in, bf16 out ---------------
__global__ __launch_bounds__(256)
void softmax_k(const float* __restrict__ S, __nv_bfloat16* __restrict__ P,
               const int* __restrict__ masks, float scale)
{
    const size_t row = blockIdx.x;
    const int b = (int)(row / SEQ);
    const float* p = S + row * (size_t)SEQ;
    __nv_bfloat16* o = P + row * (size_t)SEQ;
    const int* mrow = masks + (size_t)b * SEQ;
    const int k0 = threadIdx.x * 8;

    __shared__ float red[256];
    float v[8];
    float mx = -3e38f;
    #pragma unroll
    for (int i = 0; i < 2; ++i) {
        float4 s4 = *reinterpret_cast<const float4*>(p + k0 + i * 4);
        int4   m4 = *reinterpret_cast<const int4*>(mrow + k0 + i * 4);
        v[i*4+0] = m4.x ? s4.x * scale : NEG_INF_V;
        v[i*4+1] = m4.y ? s4.y * scale : NEG_INF_V;
        v[i*4+2] = m4.z ? s4.z * scale : NEG_INF_V;
        v[i*4+3] = m4.w ? s4.w * scale : NEG_INF_V;
    }
    #pragma unroll
    for (int i = 0; i < 8; ++i) mx = fmaxf(mx, v[i]);
    red[threadIdx.x] = mx;
    __syncthreads();
    #pragma unroll
    for (int s2 = 128; s2 > 0; s2 >>= 1) {
        if (threadIdx.x < s2)
            red[threadIdx.x] = fmaxf(red[threadIdx.x], red[threadIdx.x + s2]);
        __syncthreads();
    }
    mx = red[0];
    __syncthreads();

    float sum = 0.f;
    #pragma unroll
    for (int i = 0; i < 8; ++i) { v[i] = __expf(v[i] - mx); sum += v[i]; }
    red[threadIdx.x] = sum;
    __syncthreads();
    #pragma unroll
    for (int s2 = 128; s2 > 0; s2 >>= 1) {
        if (threadIdx.x < s2) red[threadIdx.x] += red[threadIdx.x + s2];
        __syncthreads();
    }
    const float inv = 1.0f / red[0];

    uint4 pk;
    __nv_bfloat162 h;
    h = __float22bfloat162_rn(make_float2(v[0]*inv, v[1]*inv)); pk.x = *reinterpret_cast<uint32_t*>(&h);
    h = __float22bfloat162_rn(make_float2(v[2]*inv, v[3]*inv)); pk.y = *reinterpret_cast<uint32_t*>(&h);
    h = __float22bfloat162_rn(make_float2(v[4]*inv, v[5]*inv)); pk.z = *reinterpret_cast<uint32_t*>(&h);
    h = __float22bfloat162_rn(make_float2(v[6]*inv, v[7]*inv)); pk.w = *reinterpret_cast<uint32_t*>(&h);
    *reinterpret_cast<uint4*>(o + k0) = pk;
}

// ---------------- residual + LayerNorm -------------------------------------
__global__ __launch_bounds__(256)
void ln_k(const float* __restrict__ X, const float* __restrict__ Cx,
          const float* __restrict__ gamma, const float* __restrict__ beta,
          float* __restrict__ out)
{
    const size_t row = blockIdx.x;
    const float* x = X  + row * (size_t)HID;
    const float* c = Cx + row * (size_t)HID;

    __shared__ float red[256];
    float v[4];
    float s = 0.f;
    #pragma unroll
    for (int i = 0; i < 4; ++i) {
        int k = threadIdx.x + i * 256;
        v[i] = x[k] + c[k];
        s += v[i];
    }
    red[threadIdx.x] = s;
    __syncthreads();
    #pragma unroll
    for (int s2 = 128; s2 > 0; s2 >>= 1) {
        if (threadIdx.x < s2) red[threadIdx.x] += red[threadIdx.x + s2];
        __syncthreads();
    }
    const float mu = red[0] * (1.0f / HID);
    __syncthreads();

    float s2v = 0.f;
    #pragma unroll
    for (int i = 0; i < 4; ++i) { float d = v[i] - mu; s2v += d * d; }
    red[threadIdx.x] = s2v;
    __syncthreads();
    #pragma unroll
    for (int s2 = 128; s2 > 0; s2 >>= 1) {
        if (threadIdx.x < s2) red[threadIdx.x] += red[threadIdx.x + s2];
        __syncthreads();
    }
    const float var = red[0] * (1.0f / HID);
    const float r = rsqrtf(var + LN_EPS);
    #pragma unroll
    for (int i = 0; i < 4; ++i) {
        int k = threadIdx.x + i * 256;
        out[row * (size_t)HID + k] = (v[i] - mu) * r * gamma[k] + beta[k];
    }
}

// ---------------- launch ---------------------------------------------------
extern "C" void kernel_launch(void* const* d_in, const int* in_sizes, int n_in,
                              void* d_out, int out_size)
{
    const float* inputs = (const float*)d_in[0];
    const int*   masks  = (const int*)  d_in[1];
    const float* Wq     = (const float*)d_in[2];
    const float* bq     = (const float*)d_in[3];
    const float* Wk     = (const float*)d_in[4];
    const float* bk     = (const float*)d_in[5];
    const float* gamma  = (const float*)d_in[6];
    const float* beta   = (const float*)d_in[7];
    float* out = (float*)d_out;

    float *Sp;
    __nv_bfloat16 *Pp, *Xbp, *XTp, *Qp, *Kp, *Wqp, *Wkp;
    cudaGetSymbolAddress((void**)&Sp,  g_S);
    cudaGetSymbolAddress((void**)&Pp,  g_P);
    cudaGetSymbolAddress((void**)&Xbp, g_Xb);
    cudaGetSymbolAddress((void**)&XTp, g_XT);
    cudaGetSymbolAddress((void**)&Qp,  g_Qb);
    cudaGetSymbolAddress((void**)&Kp,  g_Kb);
    cudaGetSymbolAddress((void**)&Wqp, g_Wq);
    cudaGetSymbolAddress((void**)&Wkp, g_Wk);

    const int M = BATCH * SEQ;                       // 16384
    const long long sSH = (long long)SEQ * HID;
    const long long sSS = (long long)SEQ * SEQ;
    const long long sHS = (long long)HID * SEQ;
    const float scale = 0.03125f;                    // 1/sqrt(1024)

    cudaFuncSetAttribute(hgemm<true,  true >, cudaFuncAttributeMaxDynamicSharedMemorySize, SMEM_GEMM);
    cudaFuncSetAttribute(hgemm<false, false>, cudaFuncAttributeMaxDynamicSharedMemorySize, SMEM_GEMM);

    // bf16 conversions / transposes
    cvt_bf16_k<<<(unsigned)((size_t)M * HID / (256 * 4)), 256>>>(inputs, Xbp);
    transpose_bf16_k<<<dim3(HID/32, SEQ/32, BATCH), 256>>>(inputs, XTp, SEQ, HID, sSH, sHS);
    transpose_bf16_k<<<dim3(HID/32, HID/32, 1), 256>>>(Wq, Wqp, HID, HID, 0, 0);
    transpose_bf16_k<<<dim3(HID/32, HID/32, 1), 256>>>(Wk, Wkp, HID, HID, 0, 0);

    // Q = X Wq + bq ; K = X Wk + bk  -> bf16
    hgemm<true, true><<<dim3(HID/GBN, M/GBM, 1), 256, SMEM_GEMM>>>(
        Xbp, Wqp, bq, Qp, M, HID, HID, 0, 0, 0);
    hgemm<true, true><<<dim3(HID/GBN, M/GBM, 1), 256, SMEM_GEMM>>>(
        Xbp, Wkp, bk, Kp, M, HID, HID, 0, 0, 0);

    // scores = Q K^T per batch -> fp32
    hgemm<false, false><<<dim3(SEQ/GBN, SEQ/GBM, BATCH), 256, SMEM_GEMM>>>(
        Qp, Kp, nullptr, Sp, SEQ, SEQ, HID, sSH, sSH, sSS);

    // masked, scaled softmax -> bf16 probs
    softmax_k<<<M, 256>>>(Sp, Pp, masks, scale);

    // context = probs @ X per batch -> fp32 (reuse g_S)
    hgemm<false, false><<<dim3(HID/GBN, SEQ/GBM, BATCH), 256, SMEM_GEMM>>>(
        Pp, XTp, nullptr, Sp, SEQ, HID, SEQ, sSS, sHS, sSH);

    // out = LN(X + context)
    ln_k<<<M, 256>>>(inputs, Sp, gamma, beta, out);
}